// round 14
// baseline (speedup 1.0000x reference)
#include <cuda_runtime.h>
#include <cuda_fp16.h>
#include <cstdint>
#include <math.h>

#define KT   16
#define NPER 16384
#define DD   256
#define NTOT (KT * NPER)

#define BM 64
#define BK 32
#define NSLICE 8

// smem (bytes): A16 x2, B16 x3, A32 x3
#define A16_STAGE 5120      // 64 rows x 80B
#define B16_STAGE 10240     // 128 rows x 80B
#define A32_STAGE 9216      // 64 rows x 144B (36 floats, pad 4)
#define A16_OFF   0
#define B16_OFF   (2 * A16_STAGE)               // 10240
#define A32_OFF   (B16_OFF + 3 * B16_STAGE)     // 40960
#define SMEM_BYTES (A32_OFF + 3 * A32_STAGE)    // 68608

__device__ int    g_inv[NTOT];
__device__ __half g_wh[KT * DD * DD];    // w in fp16

// ---------------------------------------------------------------- prep
__global__ void prep_kernel(const int* __restrict__ perm, const float* __restrict__ w) {
    int i = blockIdx.x * blockDim.x + threadIdx.x;
    if (i < NTOT) g_inv[perm[i]] = i;
    if (i < KT * DD * DD) g_wh[i] = __float2half_rn(w[i]);
}

// ---------------------------------------------------------------- helpers
__device__ __forceinline__ uint32_t smem_u32(const void* p) {
    uint32_t a;
    asm("{ .reg .u64 t; cvta.to.shared.u64 t, %1; cvt.u32.u64 %0, t; }" : "=r"(a) : "l"(p));
    return a;
}
__device__ __forceinline__ void cp16(uint32_t sa, const void* ga) {
    asm volatile("cp.async.cg.shared.global [%0], [%1], 16;" :: "r"(sa), "l"(ga));
}
__device__ __forceinline__ void ldmx4(uint32_t* r, uint32_t addr) {
    asm volatile("ldmatrix.sync.aligned.m8n8.x4.shared.b16 {%0,%1,%2,%3}, [%4];"
                 : "=r"(r[0]), "=r"(r[1]), "=r"(r[2]), "=r"(r[3]) : "r"(addr));
}
__device__ __forceinline__ void mma_f16(float* c, const uint32_t* a, const uint32_t* b) {
    asm volatile(
        "mma.sync.aligned.m16n8k16.row.col.f32.f16.f16.f32 "
        "{%0,%1,%2,%3}, {%4,%5,%6,%7}, {%8,%9}, {%0,%1,%2,%3};"
        : "+f"(c[0]), "+f"(c[1]), "+f"(c[2]), "+f"(c[3])
        : "r"(a[0]), "r"(a[1]), "r"(a[2]), "r"(a[3]), "r"(b[0]), "r"(b[1]));
}
__device__ __forceinline__ float fast_tanh(float v) {
    v = fminf(9.0f, fmaxf(-9.0f, v));
    float e = __expf(2.0f * v);
    return __fdividef(e - 1.0f, e + 1.0f);
}
__device__ __forceinline__ uint32_t h2u(__half2 h) {
    return *reinterpret_cast<uint32_t*>(&h);
}

// cp.async for one slice: A fp32 64x32 (8 KB) + B fp16 128x32 (8 KB), 256 thr
__device__ __forceinline__ void issue_slice(uint32_t sb, const float* xg,
                                            const __half* wh, int s, int buf, int tid) {
    uint32_t a32 = sb + A32_OFF + buf * A32_STAGE;
    #pragma unroll
    for (int t = 0; t < 2; ++t) {
        int q = tid + t * 256;          // 0..511
        int m = q >> 3, j = q & 7;
        cp16(a32 + m * 144 + j * 16, xg + m * DD + s * BK + j * 4);
    }
    uint32_t b16 = sb + B16_OFF + buf * B16_STAGE;
    #pragma unroll
    for (int t = 0; t < 2; ++t) {
        int q = tid + t * 256;          // 0..511
        int n = q >> 2, c = q & 3;
        cp16(b16 + n * 80 + c * 16, wh + n * DD + s * BK + c * 8);
    }
}

// ---------------------------------------------------------------- main kernel
// 256 threads, warp grid 2(m) x 4(n); warp tile 32x32; BM=64, BN=128;
// 3 CTAs/SM target. Round-8 pipeline: 3-stage deep-prefetch + in-smem cvt.
__global__ __launch_bounds__(256, 3) void gemm_mma_f16(
    const float* __restrict__ x, float* __restrict__ out)
{
    extern __shared__ char smc[];
    const uint32_t sb = smem_u32(smc);

    const int tid  = threadIdx.x;
    const int lane = tid & 31;
    const int grp  = lane >> 2;      // 0..7
    const int qc   = lane & 3;       // 0..3
    const int wid  = tid >> 5;
    const int wm   = wid >> 2;       // 0..1
    const int wn   = wid & 3;        // 0..3

    const int half = blockIdx.x;     // 0..1   (N half)
    const int mt   = blockIdx.y;     // 0..255 (M tile of 64 rows)
    const int kz   = blockIdx.z;     // 0..15  (type)

    const float*  xg = x    + (size_t)kz * NPER * DD + (size_t)mt * BM * DD;
    const __half* wh = g_wh + (size_t)kz * DD * DD   + (size_t)half * 128 * DD;

    // ldmatrix per-lane offsets (bytes)
    const int aRow = wm * 32 + ((lane >> 3) & 1) * 8 + (lane & 7);
    const uint32_t aOffL = (uint32_t)(aRow * 80 + (lane >> 4) * 16);
    const int bRow = wn * 32 + (lane >> 4) * 8 + (lane & 7);
    const uint32_t bOffL = (uint32_t)(bRow * 80 + ((lane >> 3) & 1) * 16);

    // cvt-phase: 8 floats per thread (64 rows x 32 floats / 256 thr)
    const int cm = tid >> 2;         // row 0..63
    const int ch = tid & 3;          // 8-float chunk

    float acc[2][4][4];
    #pragma unroll
    for (int i = 0; i < 2; i++)
        #pragma unroll
        for (int j = 0; j < 4; j++)
            #pragma unroll
            for (int q = 0; q < 4; q++)
                acc[i][j][q] = 0.0f;

    issue_slice(sb, xg, wh, 0, 0, tid);
    asm volatile("cp.async.commit_group;");
    issue_slice(sb, xg, wh, 1, 1, tid);
    asm volatile("cp.async.commit_group;");

    int bufC = 0;
    for (int s = 0; s < NSLICE; ++s) {
        if (s < NSLICE - 1) asm volatile("cp.async.wait_group 1;");
        else                asm volatile("cp.async.wait_group 0;");
        __syncthreads();

        // deep prefetch: issue slice s+2 before cvt/compute
        if (s + 2 < NSLICE) {
            int bufP = bufC + 2 >= 3 ? bufC - 1 : bufC + 2;
            issue_slice(sb, xg, wh, s + 2, bufP, tid);
            asm volatile("cp.async.commit_group;");
        }

        // ---- convert A fp32 -> fp16 tile (8 floats / thread) ----
        {
            const float4* src = reinterpret_cast<const float4*>(
                smc + A32_OFF + bufC * A32_STAGE + cm * 144 + ch * 32);
            float4 v0 = src[0], v1 = src[1];
            uint4 u;
            u.x = h2u(__floats2half2_rn(v0.x, v0.y));
            u.y = h2u(__floats2half2_rn(v0.z, v0.w));
            u.z = h2u(__floats2half2_rn(v1.x, v1.y));
            u.w = h2u(__floats2half2_rn(v1.z, v1.w));
            *reinterpret_cast<uint4*>(
                smc + A16_OFF + (s & 1) * A16_STAGE + cm * 80 + ch * 16) = u;
        }
        __syncthreads();

        // ---- compute: 2 k16-steps, 8 MMA each ----
        const uint32_t aBase = sb + A16_OFF + (uint32_t)(s & 1) * A16_STAGE + aOffL;
        const uint32_t bBase = sb + B16_OFF + (uint32_t)bufC * B16_STAGE + bOffL;

        #pragma unroll
        for (int ks = 0; ks < 2; ++ks) {
            uint32_t b0[4], b1[4];
            ldmx4(b0, bBase + ks * 32);
            ldmx4(b1, bBase + 16 * 80 + ks * 32);
            #pragma unroll
            for (int mb = 0; mb < 2; ++mb) {
                uint32_t a[4];
                ldmx4(a, aBase + mb * (16 * 80) + ks * 32);
                mma_f16(acc[mb][0], a, b0);
                mma_f16(acc[mb][1], a, b0 + 2);
                mma_f16(acc[mb][2], a, b1);
                mma_f16(acc[mb][3], a, b1 + 2);
            }
        }

        bufC = (bufC == 2) ? 0 : bufC + 1;
    }

    // ---------------- epilogue: tanh + permuted scatter ----------------
    #pragma unroll
    for (int mb = 0; mb < 2; ++mb) {
        int mrow = mt * BM + wm * 32 + mb * 16 + grp;
        int ra = g_inv[kz * NPER + mrow];
        int rb = g_inv[kz * NPER + mrow + 8];
        #pragma unroll
        for (int nb = 0; nb < 4; ++nb) {
            int col = half * 128 + wn * 32 + nb * 8 + 2 * qc;
            float2 v0, v1;
            v0.x = fast_tanh(acc[mb][nb][0]);
            v0.y = fast_tanh(acc[mb][nb][1]);
            v1.x = fast_tanh(acc[mb][nb][2]);
            v1.y = fast_tanh(acc[mb][nb][3]);
            *reinterpret_cast<float2*>(out + (size_t)ra * DD + col) = v0;
            *reinterpret_cast<float2*>(out + (size_t)rb * DD + col) = v1;
        }
    }
}

// ---------------------------------------------------------------- launch
extern "C" void kernel_launch(void* const* d_in, const int* in_sizes, int n_in,
                              void* d_out, int out_size)
{
    const float* x    = (const float*)d_in[0];
    const float* w    = (const float*)d_in[1];
    const int*   perm = (const int*)d_in[2];
    float*       out  = (float*)d_out;

    cudaFuncSetAttribute(gemm_mma_f16,
                         cudaFuncAttributeMaxDynamicSharedMemorySize, SMEM_BYTES);

    prep_kernel<<<(KT * DD * DD + 255) / 256, 256>>>(perm, w);

    dim3 grid(2, 256, 16);
    gemm_mma_f16<<<grid, 256, SMEM_BYTES>>>(x, out);
}

// round 15
// speedup vs baseline: 1.2523x; 1.2523x over previous
#include <cuda_runtime.h>
#include <cuda_fp16.h>
#include <cstdint>
#include <math.h>

#define KT   16
#define NPER 16384
#define DD   256
#define NTOT (KT * NPER)

#define BK 32
#define NSLICE 8

// smem (bytes): A16 x2 (parity), B16 x4 (ring s&3), A32 x3 (ring s%3, swizzled)
#define A16_STAGE 10240     // 128 rows x 80B
#define B16_STAGE 10240
#define A32_STAGE 16384     // 128 rows x 128B, XOR-swizzled
#define A16_OFF   0
#define B16_OFF   (2 * A16_STAGE)               // 20480
#define A32_OFF   (B16_OFF + 4 * B16_STAGE)     // 61440
#define SMEM_BYTES (A32_OFF + 3 * A32_STAGE)    // 110592

__device__ int    g_inv[NTOT];
__device__ __half g_wh[KT * DD * DD];    // w in fp16

// ---------------------------------------------------------------- prep
__global__ void prep_kernel(const int* __restrict__ perm, const float* __restrict__ w) {
    int i = blockIdx.x * blockDim.x + threadIdx.x;
    if (i < NTOT) g_inv[perm[i]] = i;
    if (i < KT * DD * DD) g_wh[i] = __float2half_rn(w[i]);
}

// ---------------------------------------------------------------- helpers
__device__ __forceinline__ uint32_t smem_u32(const void* p) {
    uint32_t a;
    asm("{ .reg .u64 t; cvta.to.shared.u64 t, %1; cvt.u32.u64 %0, t; }" : "=r"(a) : "l"(p));
    return a;
}
__device__ __forceinline__ void cp16(uint32_t sa, const void* ga) {
    asm volatile("cp.async.cg.shared.global [%0], [%1], 16;" :: "r"(sa), "l"(ga));
}
__device__ __forceinline__ void ldmx4(uint32_t* r, uint32_t addr) {
    asm volatile("ldmatrix.sync.aligned.m8n8.x4.shared.b16 {%0,%1,%2,%3}, [%4];"
                 : "=r"(r[0]), "=r"(r[1]), "=r"(r[2]), "=r"(r[3]) : "r"(addr));
}
__device__ __forceinline__ void mma_f16(float* c, const uint32_t* a, const uint32_t* b) {
    asm volatile(
        "mma.sync.aligned.m16n8k16.row.col.f32.f16.f16.f32 "
        "{%0,%1,%2,%3}, {%4,%5,%6,%7}, {%8,%9}, {%0,%1,%2,%3};"
        : "+f"(c[0]), "+f"(c[1]), "+f"(c[2]), "+f"(c[3])
        : "r"(a[0]), "r"(a[1]), "r"(a[2]), "r"(a[3]), "r"(b[0]), "r"(b[1]));
}
__device__ __forceinline__ float fast_tanh(float v) {
    v = fminf(9.0f, fmaxf(-9.0f, v));
    float e = __expf(2.0f * v);
    return __fdividef(e - 1.0f, e + 1.0f);
}
__device__ __forceinline__ uint32_t h2u(__half2 h) {
    return *reinterpret_cast<uint32_t*>(&h);
}

// cp.async for slice s: A fp32 128x32 swizzled (16 KB) + B fp16 128x32 (8 KB)
__device__ __forceinline__ void issue_slice(uint32_t sb, const float* xg,
                                            const __half* wh, int s, int tid) {
    uint32_t a32 = sb + A32_OFF + (uint32_t)(s % 3) * A32_STAGE;
    #pragma unroll
    for (int t = 0; t < 4; ++t) {
        int q = tid + t * 256;          // 0..1023
        int m = q >> 3, j = q & 7;
        cp16(a32 + m * 128 + ((j ^ (m & 7)) << 4), xg + m * DD + s * BK + j * 4);
    }
    uint32_t b16 = sb + B16_OFF + (uint32_t)(s & 3) * B16_STAGE;
    #pragma unroll
    for (int t = 0; t < 2; ++t) {
        int q = tid + t * 256;          // 0..511
        int n = q >> 2, c = q & 3;
        cp16(b16 + n * 80 + c * 16, wh + n * DD + s * BK + c * 8);
    }
}

// ---------------------------------------------------------------- main kernel
// 256 threads, warp grid 2(m) x 4(n); warp tile 64x32; single fused phase:
// cvt(s+1) interleaved with ldmatrix+MMA(s); ONE __syncthreads per slice.
__global__ __launch_bounds__(256, 2) void gemm_fused_f16(
    const float* __restrict__ x, float* __restrict__ out)
{
    extern __shared__ char smc[];
    const uint32_t sb = smem_u32(smc);

    const int tid  = threadIdx.x;
    const int lane = tid & 31;
    const int grp  = lane >> 2;      // 0..7
    const int qc   = lane & 3;       // 0..3
    const int wid  = tid >> 5;
    const int wm   = wid >> 2;       // 0..1
    const int wn   = wid & 3;        // 0..3

    const int half = blockIdx.x;     // 0..1  (N half)
    const int mt   = blockIdx.y;     // 0..127 (M tile)
    const int kz   = blockIdx.z;     // 0..15  (type)

    const float*  xg = x    + (size_t)kz * NPER * DD + (size_t)mt * 128 * DD;
    const __half* wh = g_wh + (size_t)kz * DD * DD   + (size_t)half * 128 * DD;

    // ldmatrix per-lane offsets (bytes)
    const int aRow = wm * 64 + ((lane >> 3) & 1) * 8 + (lane & 7);
    const uint32_t aOffL = (uint32_t)(aRow * 80 + (lane >> 4) * 16);
    const int bRow = wn * 32 + (lane >> 4) * 8 + (lane & 7);
    const uint32_t bOffL = (uint32_t)(bRow * 80 + ((lane >> 3) & 1) * 16);

    // cvt coords: 16 floats per thread (row cm, half ch)
    const int cm = tid >> 1;
    const int ch = tid & 1;

    float acc[4][4][4];
    #pragma unroll
    for (int i = 0; i < 4; i++)
        #pragma unroll
        for (int j = 0; j < 4; j++)
            #pragma unroll
            for (int q = 0; q < 4; q++)
                acc[i][j][q] = 0.0f;

    // ---------------- prologue ----------------
    issue_slice(sb, xg, wh, 0, tid);
    asm volatile("cp.async.commit_group;");
    issue_slice(sb, xg, wh, 1, tid);
    asm volatile("cp.async.commit_group;");
    asm volatile("cp.async.wait_group 1;");   // slice 0 landed
    __syncthreads();

    // cvt(0): A32[0] -> A16[0]
    {
        const char* a32 = smc + A32_OFF;
        char*       a16 = smc + A16_OFF;
        float4 v[4];
        #pragma unroll
        for (int j = 0; j < 4; ++j) {
            int jj = ch * 4 + j;
            v[j] = *reinterpret_cast<const float4*>(a32 + cm * 128 + ((jj ^ (cm & 7)) << 4));
        }
        uint4 u0, u1;
        u0.x = h2u(__floats2half2_rn(v[0].x, v[0].y));
        u0.y = h2u(__floats2half2_rn(v[0].z, v[0].w));
        u0.z = h2u(__floats2half2_rn(v[1].x, v[1].y));
        u0.w = h2u(__floats2half2_rn(v[1].z, v[1].w));
        u1.x = h2u(__floats2half2_rn(v[2].x, v[2].y));
        u1.y = h2u(__floats2half2_rn(v[2].z, v[2].w));
        u1.z = h2u(__floats2half2_rn(v[3].x, v[3].y));
        u1.w = h2u(__floats2half2_rn(v[3].z, v[3].w));
        uint4* dst = reinterpret_cast<uint4*>(a16 + cm * 80 + ch * 32);
        dst[0] = u0;
        dst[1] = u1;
    }
    issue_slice(sb, xg, wh, 2, tid);
    asm volatile("cp.async.commit_group;");

    // ---------------- fused main loop ----------------
    #pragma unroll
    for (int s = 0; s < NSLICE; ++s) {
        if (s < 6) asm volatile("cp.async.wait_group 1;");   // slices <= s+1 done
        else       asm volatile("cp.async.wait_group 0;");
        __syncthreads();   // publishes cvt(s) STS + cp.async of slices <= s+1

        if (s + 3 < NSLICE) {
            issue_slice(sb, xg, wh, s + 3, tid);
            asm volatile("cp.async.commit_group;");
        }

        const uint32_t aBase = sb + A16_OFF + (uint32_t)(s & 1) * A16_STAGE + aOffL;
        const uint32_t bBase = sb + B16_OFF + (uint32_t)(s & 3) * B16_STAGE + bOffL;
        const bool doCvt = (s + 1 < NSLICE);
        const char* a32n = smc + A32_OFF + ((s + 1) % 3) * A32_STAGE;
        char*       a16n = smc + A16_OFF + ((s + 1) & 1) * A16_STAGE;

        // cvt loads for slice s+1 (independent of MMA stream below)
        float4 v[4];
        if (doCvt) {
            #pragma unroll
            for (int j = 0; j < 4; ++j) {
                int jj = ch * 4 + j;
                v[j] = *reinterpret_cast<const float4*>(
                    a32n + cm * 128 + ((jj ^ (cm & 7)) << 4));
            }
        }

        // ks = 0
        {
            uint32_t b0[4], b1[4];
            ldmx4(b0, bBase);
            ldmx4(b1, bBase + 16 * 80);
            #pragma unroll
            for (int mb = 0; mb < 4; ++mb) {
                uint32_t a[4];
                ldmx4(a, aBase + mb * (16 * 80));
                mma_f16(acc[mb][0], a, b0);
                mma_f16(acc[mb][1], a, b0 + 2);
                mma_f16(acc[mb][2], a, b1);
                mma_f16(acc[mb][3], a, b1 + 2);
            }
        }

        // cvt converts + stores (fills tensor-idle cycles)
        if (doCvt) {
            uint4 u0, u1;
            u0.x = h2u(__floats2half2_rn(v[0].x, v[0].y));
            u0.y = h2u(__floats2half2_rn(v[0].z, v[0].w));
            u0.z = h2u(__floats2half2_rn(v[1].x, v[1].y));
            u0.w = h2u(__floats2half2_rn(v[1].z, v[1].w));
            u1.x = h2u(__floats2half2_rn(v[2].x, v[2].y));
            u1.y = h2u(__floats2half2_rn(v[2].z, v[2].w));
            u1.z = h2u(__floats2half2_rn(v[3].x, v[3].y));
            u1.w = h2u(__floats2half2_rn(v[3].z, v[3].w));
            uint4* dst = reinterpret_cast<uint4*>(a16n + cm * 80 + ch * 32);
            dst[0] = u0;
            dst[1] = u1;
        }

        // ks = 1
        {
            uint32_t b0[4], b1[4];
            ldmx4(b0, bBase + 32);
            ldmx4(b1, bBase + 16 * 80 + 32);
            #pragma unroll
            for (int mb = 0; mb < 4; ++mb) {
                uint32_t a[4];
                ldmx4(a, aBase + mb * (16 * 80) + 32);
                mma_f16(acc[mb][0], a, b0);
                mma_f16(acc[mb][1], a, b0 + 2);
                mma_f16(acc[mb][2], a, b1);
                mma_f16(acc[mb][3], a, b1 + 2);
            }
        }
    }

    // ---------------- epilogue: tanh + permuted scatter ----------------
    #pragma unroll
    for (int mb = 0; mb < 4; ++mb) {
        int mrow = mt * 128 + wm * 64 + mb * 16 + grp;
        int ra = g_inv[kz * NPER + mrow];
        int rb = g_inv[kz * NPER + mrow + 8];
        #pragma unroll
        for (int nb = 0; nb < 4; ++nb) {
            int col = half * 128 + wn * 32 + nb * 8 + 2 * qc;
            float2 v0, v1;
            v0.x = fast_tanh(acc[mb][nb][0]);
            v0.y = fast_tanh(acc[mb][nb][1]);
            v1.x = fast_tanh(acc[mb][nb][2]);
            v1.y = fast_tanh(acc[mb][nb][3]);
            *reinterpret_cast<float2*>(out + (size_t)ra * DD + col) = v0;
            *reinterpret_cast<float2*>(out + (size_t)rb * DD + col) = v1;
        }
    }
}

// ---------------------------------------------------------------- launch
extern "C" void kernel_launch(void* const* d_in, const int* in_sizes, int n_in,
                              void* d_out, int out_size)
{
    const float* x    = (const float*)d_in[0];
    const float* w    = (const float*)d_in[1];
    const int*   perm = (const int*)d_in[2];
    float*       out  = (float*)d_out;

    cudaFuncSetAttribute(gemm_fused_f16,
                         cudaFuncAttributeMaxDynamicSharedMemorySize, SMEM_BYTES);

    prep_kernel<<<(KT * DD * DD + 255) / 256, 256>>>(perm, w);

    dim3 grid(2, 128, 16);
    gemm_fused_f16<<<grid, 256, SMEM_BYTES>>>(x, out);
}